// round 14
// baseline (speedup 1.0000x reference)
#include <cuda_runtime.h>
#include <cstdint>

#define BB 32
#define NVV 8192
#define NEE 65536
#define ELLMAX 48
#define KPAIR 24        // ELLMAX/2 index pairs
#define NSUB 8
#define NCTA 4          // CTAs per batch = one cluster
#define TPB 512
#define VPT 4           // gather vertices per thread
#define NCH 16          // full-vector chunks per thread (NVV/TPB)
#define NW 16           // warps per CTA
#define CG_ITERS 20
#define DTf 0.01f
#define KSf 10000.0f
#define CS (BB*NVV)
#define NVP 8208        // NVV + 16 sentinel slots for smem p array

// ---------------- scratch ----------------------------------------------------
__device__ float    g_pos[3*CS];       // sorted space, planar
__device__ float    g_v0 [3*CS];
__device__ float    g_r  [3*CS];
__device__ float4   g_Ap4[2][CS];      // vectorized Ap, double-buffered
__device__ int      g_cnt[NVV];
__device__ int      g_deg[NVV];
__device__ int      g_nbr[ELLMAX*NVV];
__device__ int      g_eid[ELLMAX*NVV];
__device__ int      g_perm[NVV];
__device__ int      g_ipos[NVV];
__device__ unsigned g_nbrp[KPAIR*NVV]; // packed sorted-position pairs (sentinel-padded)
__device__ float    g_mass_p[NVV];
__device__ int      g_deg_p[NVV];
__device__ float    g_rest[(size_t)BB*ELLMAX*NVV];
__device__ unsigned g_gbar;

// ---------------- helpers ----------------------------------------------------
__device__ __forceinline__ void gpu_spin_barrier(unsigned* bar, unsigned target) {
    __syncthreads();
    if (threadIdx.x == 0) {
        asm volatile("red.release.gpu.add.u32 [%0], 1;" :: "l"(bar) : "memory");
        unsigned v;
        do {
            asm volatile("ld.acquire.gpu.u32 %0, [%1];" : "=r"(v) : "l"(bar) : "memory");
        } while (v < target);
    }
    __syncthreads();
}

#define CLUSTER_SYNC_() do { \
    asm volatile("barrier.cluster.arrive.aligned;" ::: "memory"); \
    asm volatile("barrier.cluster.wait.aligned;"   ::: "memory"); \
} while (0)

__device__ __forceinline__ float dsmem_read_f32(uint32_t saddr, uint32_t rank) {
    uint32_t ra; float v;
    asm volatile("mapa.shared::cluster.u32 %0, %1, %2;" : "=r"(ra) : "r"(saddr), "r"(rank));
    asm volatile("ld.shared::cluster.f32 %0, [%1];" : "=f"(v) : "r"(ra));
    return v;
}

// log-tree reduce over 512 threads (16 warps); result valid on thread 0
__device__ __forceinline__ float bredt(float a, float* s16) {
    int lane = threadIdx.x & 31, w = threadIdx.x >> 5;
    #pragma unroll
    for (int o = 16; o; o >>= 1) a += __shfl_down_sync(0xffffffffu, a, o);
    if (lane == 0) s16[w] = a;
    __syncthreads();
    float t = 0.f;
    if (w == 0) {
        t = (lane < NW) ? s16[lane] : 0.f;
        #pragma unroll
        for (int o = 8; o; o >>= 1) t += __shfl_down_sync(0xffffffffu, t, o);
    }
    return t;
}

// ---------------- launch 0: zero ---------------------------------------------
__global__ void k_pre() {
    int v = blockIdx.x * blockDim.x + threadIdx.x;
    if (v < NVV) g_cnt[v] = 0;
    if (v == 0)  g_gbar = 0u;
}

// ---------------- launch 1: adjacency fill -----------------------------------
__global__ void k_fill(const int* __restrict__ ei, const int* __restrict__ ej) {
    int e = blockIdx.x * blockDim.x + threadIdx.x;
    if (e >= NEE) return;
    int i = ei[e], j = ej[e];
    int si = atomicAdd(&g_cnt[i], 1);
    if (si < ELLMAX) { g_nbr[si*NVV + i] = j; g_eid[si*NVV + i] = e; }
    int sj = atomicAdd(&g_cnt[j], 1);
    if (sj < ELLMAX) { g_nbr[sj*NVV + j] = i; g_eid[sj*NVV + j] = e; }
}

// ---------------- launch 2: fused setup ---------------------------------------
__global__ void k_setup(const float* __restrict__ mass,
                        const float* __restrict__ pos0, const float* __restrict__ vel0,
                        const float* __restrict__ rest_len, const float* __restrict__ act) {
    const int gtid = blockIdx.x * blockDim.x + threadIdx.x;
    const int nthr = gridDim.x * blockDim.x;

    // phase 1: deterministic per-vertex adjacency sort
    for (int v = gtid; v < NVV; v += nthr) {
        int d = min(g_cnt[v], ELLMAX);
        g_deg[v] = d;
        long long key[ELLMAX];
        for (int k = 0; k < d; k++)
            key[k] = ((long long)g_nbr[k*NVV + v] << 32) | (unsigned)g_eid[k*NVV + v];
        for (int a = 1; a < d; a++) {
            long long t = key[a]; int c = a - 1;
            while (c >= 0 && key[c] > t) { key[c+1] = key[c]; c--; }
            key[c+1] = t;
        }
        for (int k = 0; k < d; k++) {
            g_nbr[k*NVV + v] = (int)(key[k] >> 32);
            g_eid[k*NVV + v] = (int)(key[k] & 0xffffffffLL);
        }
    }
    gpu_spin_barrier(&g_gbar, gridDim.x * 1u);

    // phase 2: stable counting sort by degree (CTA 0)
    if (blockIdx.x == 0) {
        __shared__ int s_cnt[64], s_off[64];
        int w = threadIdx.x >> 5, l = threadIdx.x & 31;
        #pragma unroll
        for (int pass = 0; pass < 2; pass++) {
            int d = w + pass*32;
            int cnt = 0;
            for (int b0 = 0; b0 < NVV; b0 += 32) {
                int dg = g_deg[b0 + l];
                unsigned m = __ballot_sync(0xffffffffu, dg == d);
                cnt += __popc(m);
            }
            if (l == 0) s_cnt[d] = cnt;
        }
        __syncthreads();
        if (threadIdx.x == 0) {
            int o = 0;
            for (int d = 0; d < 64; d++) { s_off[d] = o; o += s_cnt[d]; }
        }
        __syncthreads();
        #pragma unroll
        for (int pass = 0; pass < 2; pass++) {
            int d = w + pass*32;
            int off = s_off[d];
            for (int b0 = 0; b0 < NVV; b0 += 32) {
                int v = b0 + l;
                int dg = g_deg[v];
                unsigned m = __ballot_sync(0xffffffffu, dg == d);
                if (dg == d) {
                    int rank = __popc(m & ((1u << l) - 1u));
                    g_perm[off + rank] = v;
                    g_ipos[v] = off + rank;
                }
                off += __popc(m);
            }
        }
    }
    gpu_spin_barrier(&g_gbar, gridDim.x * 2u);

    // phase 3: sorted-space tables; odd tails padded with sentinel index NVV
    for (int p = gtid; p < NVV; p += nthr) {
        int v = g_perm[p];
        g_mass_p[p] = mass[v];
        int d = g_deg[v];
        g_deg_p[p] = d;
        for (int kp = 0; kp < KPAIR; kp++) {
            unsigned lo = (2*kp   < d) ? (unsigned)g_ipos[g_nbr[(2*kp  )*NVV + v]] : (unsigned)NVV;
            unsigned hi = (2*kp+1 < d) ? (unsigned)g_ipos[g_nbr[(2*kp+1)*NVV + v]] : (unsigned)NVV;
            g_nbrp[kp*NVV + p] = lo | (hi << 16);
        }
    }
    for (int idx = gtid; idx < CS; idx += nthr) {
        int p = idx & (NVV-1), b = idx >> 13;
        int v = g_perm[p];
        size_t src = ((size_t)b*NVV + v)*3;
        #pragma unroll
        for (int c = 0; c < 3; c++) {
            g_pos[c*CS + idx] = pos0[src + c];
            g_v0 [c*CS + idx] = vel0[src + c];
        }
    }
    for (int idx = gtid; idx < BB*NVV; idx += nthr) {
        int p = idx & (NVV-1), b = idx >> 13;
        int v = g_perm[p];
        int d = g_deg[v];
        for (int k = 0; k < d; k++) {
            int e = g_eid[k*NVV + v];
            g_rest[((size_t)b*ELLMAX + k)*NVV + p] = rest_len[e] * (1.f + act[(size_t)b*NEE + e]);
        }
    }
}

// ---------------- launch 3: persistent clustered solver ------------------------
__global__ void __launch_bounds__(TPB, 1) __cluster_dims__(NCTA, 1, 1)
k_main(float* __restrict__ out) {
    extern __shared__ float4 smv[];
    float4* s_p = smv;                    // NVP float4 (incl. sentinel) ~128 KB
    __shared__ float s16[NW];
    __shared__ float s_ab[2];
    __shared__ float s_rs;
    __shared__ float s_mail[2];           // pAp partial mailbox, parity-buffered

    const int tid = threadIdx.x, cx = blockIdx.x, b = blockIdx.y;
    const int w = tid >> 5, l = tid & 31;
    const int base = b*NVV;

    // zero sentinel slots (never rewritten: updates touch [0,NVV) only)
    if (tid < NVP - NVV) s_p[NVV + tid] = make_float4(0.f, 0.f, 0.f, 0.f);

    // gather ownership: q = degree-quartile -> balanced warps & CTAs
    int pq[VPT], dq[VPT];
    float mmq[VPT];
    float PO[VPT][3], X[VPT][3];
    #pragma unroll
    for (int q = 0; q < VPT; q++) {
        int c = q*(NW*NCTA) + w*NCTA + cx;
        int p = c*32 + l;
        pq[q] = p;
        dq[q] = g_deg_p[p];
        mmq[q] = g_mass_p[p];
        int i = base + p;
        PO[q][0] = g_pos[i]; PO[q][1] = g_pos[CS+i]; PO[q][2] = g_pos[2*CS+i];
        X [q][0] = g_v0[i];  X [q][1] = g_v0[CS+i];  X [q][2] = g_v0[2*CS+i];
    }

    // register-resident residual: chunk j covers vertex j*TPB + tid
    float rX[NCH], rY[NCH], rZ[NCH];

    for (int s = 0; s < NSUB; s++) {
        // ---- stage pos into p region ----
        #pragma unroll
        for (int j = 0; j < NCH; j++) {
            int p = j*TPB + tid, i = base + p;
            s_p[p] = make_float4(__ldcg(&g_pos[i]), __ldcg(&g_pos[CS+i]),
                                 __ldcg(&g_pos[2*CS+i]), 0.f);
        }
        __syncthreads();

        // ---- force, b = m v + dt f -> g_r slice (guarded tail) ----
        #pragma unroll
        for (int q = 0; q < VPT; q++) {
            int p = pq[q], i = base + p, d = dq[q];
            int np = (d + 1) >> 1;
            float fx = 0.f, fy = 0.f, fz = 0.f;
            unsigned cur = g_nbrp[p];
            for (int kp = 0; kp < np; kp++) {
                unsigned nxt = (kp+1 < np) ? g_nbrp[(kp+1)*NVV + p] : 0u;
                int u0 = cur & 0xffffu, u1 = cur >> 16;
                {
                    float4 t = s_p[u0];
                    float dx = PO[q][0] - t.x, dy = PO[q][1] - t.y, dz = PO[q][2] - t.z;
                    float len = sqrtf(dx*dx + dy*dy + dz*dz);
                    float rr = g_rest[((size_t)b*ELLMAX + 2*kp)*NVV + p];
                    float cc = -KSf * (len - rr) / fmaxf(len, 1e-6f);
                    fx += cc*dx; fy += cc*dy; fz += cc*dz;
                }
                if (2*kp + 1 < d) {
                    float4 t = s_p[u1];
                    float dx = PO[q][0] - t.x, dy = PO[q][1] - t.y, dz = PO[q][2] - t.z;
                    float len = sqrtf(dx*dx + dy*dy + dz*dz);
                    float rr = g_rest[((size_t)b*ELLMAX + 2*kp+1)*NVV + p];
                    float cc = -KSf * (len - rr) / fmaxf(len, 1e-6f);
                    fx += cc*dx; fy += cc*dy; fz += cc*dz;
                }
                cur = nxt;
            }
            float bx = mmq[q]*X[q][0] + DTf*fx;
            float by = mmq[q]*X[q][1] + DTf*(fy + mmq[q]*(-9.8f));
            float bz = mmq[q]*X[q][2] + DTf*fz;
            X[q][0] = 0.f; X[q][1] = 0.f; X[q][2] = 0.f;
            __stcg(&g_r[i], bx); __stcg(&g_r[CS+i], by); __stcg(&g_r[2*CS+i], bz);
        }
        CLUSTER_SYNC_();

        // ---- stage r -> registers, p -> smem; rs0 locally ----
        float rs_loc = 0.f;
        #pragma unroll
        for (int j = 0; j < NCH; j++) {
            int p = j*TPB + tid, i = base + p;
            float rx = __ldcg(&g_r[i]);
            float ry = __ldcg(&g_r[CS+i]);
            float rz = __ldcg(&g_r[2*CS+i]);
            rX[j] = rx; rY[j] = ry; rZ[j] = rz;
            s_p[p] = make_float4(rx, ry, rz, 0.f);
            rs_loc += rx*rx + ry*ry + rz*rz;
        }
        __syncthreads();
        {
            float t = bredt(rs_loc, s16);
            if (tid == 0) s_rs = t;
        }
        __syncthreads();

        // ---- CG iterations ----
        for (int it = 0; it < CG_ITERS; it++) {
            const int par = it & 1;
            float4* Ap = g_Ap4[par];

            // matvec: sentinel-padded, one LDS.128 per neighbor
            float pap = 0.f;
            #pragma unroll
            for (int q = 0; q < VPT; q++) {
                int p = pq[q], i = base + p, d = dq[q];
                int np = (d + 1) >> 1;
                float sx = 0.f, sy = 0.f, sz = 0.f;
                unsigned cur = g_nbrp[p];
                for (int kp = 0; kp < np; kp++) {
                    unsigned nxt = (kp+1 < np) ? g_nbrp[(kp+1)*NVV + p] : 0u;
                    int u0 = cur & 0xffffu, u1 = cur >> 16;
                    float4 t0 = s_p[u0];
                    sx += t0.x; sy += t0.y; sz += t0.z;
                    float4 t1 = s_p[u1];            // sentinel -> (+0,+0,+0), exact
                    sx += t1.x; sy += t1.y; sz += t1.z;
                    cur = nxt;
                }
                float4 pv = s_p[p];
                float md = mmq[q] + (float)d;
                float ax = md*pv.x - sx;
                float ay = md*pv.y - sy;
                float az = md*pv.z - sz;
                __stcg(&Ap[i], make_float4(ax, ay, az, 0.f));
                pap += pv.x*ax + pv.y*ay + pv.z*az;
            }
            {
                float t = bredt(pap, s16);
                if (tid == 0) s_mail[par] = t;
            }
            CLUSTER_SYNC_();                     // publishes s_mail + Ap slices

            // alpha: lanes 0..3 of warp 0 read the 4 rank mailboxes in parallel
            if (w == 0) {
                float v = 0.f;
                if (l < NCTA) {
                    uint32_t ma = (uint32_t)__cvta_generic_to_shared(&s_mail[par]);
                    v = dsmem_read_f32(ma, (uint32_t)l);
                }
                #pragma unroll
                for (int o = 2; o; o >>= 1) v += __shfl_down_sync(0xffffffffu, v, o);
                if (l == 0) s_ab[0] = s_rs / (v + 1e-12f);
            }
            __syncthreads();
            float alpha = s_ab[0];

            // x += alpha p (own slice)
            #pragma unroll
            for (int q = 0; q < VPT; q++) {
                float4 pv = s_p[pq[q]];
                X[q][0] += alpha*pv.x; X[q][1] += alpha*pv.y; X[q][2] += alpha*pv.z;
            }

            if (it < CG_ITERS - 1) {
                // sweep1 (registers only): r -= alpha Ap; rs_new from stored r
                float rsn_loc = 0.f;
                #pragma unroll
                for (int j = 0; j < NCH; j++) {
                    int i = base + j*TPB + tid;
                    float4 a4 = __ldcg(&Ap[i]);
                    float rx = rX[j] - alpha*a4.x;
                    float ry = rY[j] - alpha*a4.y;
                    float rz = rZ[j] - alpha*a4.z;
                    rX[j] = rx; rY[j] = ry; rZ[j] = rz;
                    rsn_loc += rx*rx + ry*ry + rz*rz;
                }
                __syncthreads();
                {
                    float t = bredt(rsn_loc, s16);
                    if (tid == 0) { s_ab[1] = t / (s_rs + 1e-12f); s_rs = t; }
                }
                __syncthreads();
                float beta = s_ab[1];
                // sweep2: p = r + beta p (r from regs; p in smem, float4)
                #pragma unroll
                for (int j = 0; j < NCH; j++) {
                    int p = j*TPB + tid;
                    float4 po = s_p[p];
                    s_p[p] = make_float4(fmaf(beta, po.x, rX[j]),
                                         fmaf(beta, po.y, rY[j]),
                                         fmaf(beta, po.z, rZ[j]), 0.f);
                }
                __syncthreads();
            }
        }

        // ---- pos += dt x ; emit trajectory ----
        #pragma unroll
        for (int q = 0; q < VPT; q++) {
            int p = pq[q], i = base + p;
            PO[q][0] += DTf*X[q][0];
            PO[q][1] += DTf*X[q][1];
            PO[q][2] += DTf*X[q][2];
            __stcg(&g_pos[i],      PO[q][0]);
            __stcg(&g_pos[CS+i],   PO[q][1]);
            __stcg(&g_pos[2*CS+i], PO[q][2]);
            int vorig = g_perm[p];
            size_t o = (((size_t)b*NSUB + s)*NVV + vorig)*3;
            out[o+0] = PO[q][0]; out[o+1] = PO[q][1]; out[o+2] = PO[q][2];
        }
        CLUSTER_SYNC_();
    }
}

// ---------------- launch -------------------------------------------------------
extern "C" void kernel_launch(void* const* d_in, const int* in_sizes, int n_in,
                              void* d_out, int out_size) {
    const float* act   = (const float*)d_in[0];
    const float* pos0  = (const float*)d_in[1];
    const float* vel0  = (const float*)d_in[2];
    const float* rlen  = (const float*)d_in[3];
    const float* mass  = (const float*)d_in[4];
    const int*   ei    = (const int*)d_in[5];
    const int*   ej    = (const int*)d_in[6];
    float*       out   = (float*)d_out;

    const int smbytes = NVP * sizeof(float4);   // ~128.3 KB
    static int attr_done = 0;
    if (!attr_done) {
        cudaFuncSetAttribute(k_main, cudaFuncAttributeMaxDynamicSharedMemorySize, smbytes);
        attr_done = 1;
    }

    k_pre  <<<(NVV+255)/256, 256>>>();
    k_fill <<<(NEE+255)/256, 256>>>(ei, ej);
    k_setup<<<32, 1024>>>(mass, pos0, vel0, rlen, act);
    k_main <<<dim3(NCTA, BB), TPB, smbytes>>>(out);
}

// round 15
// speedup vs baseline: 1.1274x; 1.1274x over previous
#include <cuda_runtime.h>
#include <cstdint>

#define BB 32
#define NVV 8192
#define NEE 65536
#define ELLMAX 48
#define KPAIR 24        // ELLMAX/2 index pairs
#define NSUB 8
#define NCTA 4          // CTAs per batch = one cluster
#define TPB 512
#define VPT 4           // gather vertices per thread
#define NCH 16          // full-vector chunks per thread (NVV/TPB)
#define NW 16           // warps per CTA
#define CG_ITERS 20
#define DTf 0.01f
#define KSf 10000.0f
#define CS (BB*NVV)
#define NVP 8208        // NVV + 16 sentinel slots for smem p arrays

// ---------------- scratch ----------------------------------------------------
__device__ float    g_pos[3*CS];       // sorted space, planar
__device__ float    g_v0 [3*CS];
__device__ float    g_r  [3*CS];
__device__ float4   g_Ap4[2][CS];      // vectorized Ap, double-buffered
__device__ int      g_cnt[NVV];
__device__ int      g_deg[NVV];
__device__ int      g_nbr[ELLMAX*NVV];
__device__ int      g_eid[ELLMAX*NVV];
__device__ int      g_perm[NVV];
__device__ int      g_ipos[NVV];
__device__ unsigned g_nbrp[KPAIR*NVV]; // packed sorted-position pairs (sentinel-padded)
__device__ float    g_mass_p[NVV];
__device__ int      g_deg_p[NVV];
__device__ float    g_rest[(size_t)BB*ELLMAX*NVV];
__device__ unsigned g_gbar;

// ---------------- helpers ----------------------------------------------------
__device__ __forceinline__ void gpu_spin_barrier(unsigned* bar, unsigned target) {
    __syncthreads();
    if (threadIdx.x == 0) {
        asm volatile("red.release.gpu.add.u32 [%0], 1;" :: "l"(bar) : "memory");
        unsigned v;
        do {
            asm volatile("ld.acquire.gpu.u32 %0, [%1];" : "=r"(v) : "l"(bar) : "memory");
        } while (v < target);
    }
    __syncthreads();
}

#define CLUSTER_SYNC_() do { \
    asm volatile("barrier.cluster.arrive.aligned;" ::: "memory"); \
    asm volatile("barrier.cluster.wait.aligned;"   ::: "memory"); \
} while (0)

__device__ __forceinline__ float dsmem_read_f32(uint32_t saddr, uint32_t rank) {
    uint32_t ra; float v;
    asm volatile("mapa.shared::cluster.u32 %0, %1, %2;" : "=r"(ra) : "r"(saddr), "r"(rank));
    asm volatile("ld.shared::cluster.f32 %0, [%1];" : "=f"(v) : "r"(ra));
    return v;
}

// log-tree reduce over 512 threads (16 warps); result valid on thread 0
__device__ __forceinline__ float bredt(float a, float* s16) {
    int lane = threadIdx.x & 31, w = threadIdx.x >> 5;
    #pragma unroll
    for (int o = 16; o; o >>= 1) a += __shfl_down_sync(0xffffffffu, a, o);
    if (lane == 0) s16[w] = a;
    __syncthreads();
    float t = 0.f;
    if (w == 0) {
        t = (lane < NW) ? s16[lane] : 0.f;
        #pragma unroll
        for (int o = 8; o; o >>= 1) t += __shfl_down_sync(0xffffffffu, t, o);
    }
    return t;
}

// ---------------- launch 0: zero ---------------------------------------------
__global__ void k_pre() {
    int v = blockIdx.x * blockDim.x + threadIdx.x;
    if (v < NVV) g_cnt[v] = 0;
    if (v == 0)  g_gbar = 0u;
}

// ---------------- launch 1: adjacency fill -----------------------------------
__global__ void k_fill(const int* __restrict__ ei, const int* __restrict__ ej) {
    int e = blockIdx.x * blockDim.x + threadIdx.x;
    if (e >= NEE) return;
    int i = ei[e], j = ej[e];
    int si = atomicAdd(&g_cnt[i], 1);
    if (si < ELLMAX) { g_nbr[si*NVV + i] = j; g_eid[si*NVV + i] = e; }
    int sj = atomicAdd(&g_cnt[j], 1);
    if (sj < ELLMAX) { g_nbr[sj*NVV + j] = i; g_eid[sj*NVV + j] = e; }
}

// ---------------- launch 2: fused setup ---------------------------------------
__global__ void k_setup(const float* __restrict__ mass,
                        const float* __restrict__ pos0, const float* __restrict__ vel0,
                        const float* __restrict__ rest_len, const float* __restrict__ act) {
    const int gtid = blockIdx.x * blockDim.x + threadIdx.x;
    const int nthr = gridDim.x * blockDim.x;

    // phase 1: deterministic per-vertex adjacency sort
    for (int v = gtid; v < NVV; v += nthr) {
        int d = min(g_cnt[v], ELLMAX);
        g_deg[v] = d;
        long long key[ELLMAX];
        for (int k = 0; k < d; k++)
            key[k] = ((long long)g_nbr[k*NVV + v] << 32) | (unsigned)g_eid[k*NVV + v];
        for (int a = 1; a < d; a++) {
            long long t = key[a]; int c = a - 1;
            while (c >= 0 && key[c] > t) { key[c+1] = key[c]; c--; }
            key[c+1] = t;
        }
        for (int k = 0; k < d; k++) {
            g_nbr[k*NVV + v] = (int)(key[k] >> 32);
            g_eid[k*NVV + v] = (int)(key[k] & 0xffffffffLL);
        }
    }
    gpu_spin_barrier(&g_gbar, gridDim.x * 1u);

    // phase 2: stable counting sort by degree (CTA 0)
    if (blockIdx.x == 0) {
        __shared__ int s_cnt[64], s_off[64];
        int w = threadIdx.x >> 5, l = threadIdx.x & 31;
        #pragma unroll
        for (int pass = 0; pass < 2; pass++) {
            int d = w + pass*32;
            int cnt = 0;
            for (int b0 = 0; b0 < NVV; b0 += 32) {
                int dg = g_deg[b0 + l];
                unsigned m = __ballot_sync(0xffffffffu, dg == d);
                cnt += __popc(m);
            }
            if (l == 0) s_cnt[d] = cnt;
        }
        __syncthreads();
        if (threadIdx.x == 0) {
            int o = 0;
            for (int d = 0; d < 64; d++) { s_off[d] = o; o += s_cnt[d]; }
        }
        __syncthreads();
        #pragma unroll
        for (int pass = 0; pass < 2; pass++) {
            int d = w + pass*32;
            int off = s_off[d];
            for (int b0 = 0; b0 < NVV; b0 += 32) {
                int v = b0 + l;
                int dg = g_deg[v];
                unsigned m = __ballot_sync(0xffffffffu, dg == d);
                if (dg == d) {
                    int rank = __popc(m & ((1u << l) - 1u));
                    g_perm[off + rank] = v;
                    g_ipos[v] = off + rank;
                }
                off += __popc(m);
            }
        }
    }
    gpu_spin_barrier(&g_gbar, gridDim.x * 2u);

    // phase 3: sorted-space tables; odd tails padded with sentinel index NVV
    for (int p = gtid; p < NVV; p += nthr) {
        int v = g_perm[p];
        g_mass_p[p] = mass[v];
        int d = g_deg[v];
        g_deg_p[p] = d;
        for (int kp = 0; kp < KPAIR; kp++) {
            unsigned lo = (2*kp   < d) ? (unsigned)g_ipos[g_nbr[(2*kp  )*NVV + v]] : (unsigned)NVV;
            unsigned hi = (2*kp+1 < d) ? (unsigned)g_ipos[g_nbr[(2*kp+1)*NVV + v]] : (unsigned)NVV;
            g_nbrp[kp*NVV + p] = lo | (hi << 16);
        }
    }
    for (int idx = gtid; idx < CS; idx += nthr) {
        int p = idx & (NVV-1), b = idx >> 13;
        int v = g_perm[p];
        size_t src = ((size_t)b*NVV + v)*3;
        #pragma unroll
        for (int c = 0; c < 3; c++) {
            g_pos[c*CS + idx] = pos0[src + c];
            g_v0 [c*CS + idx] = vel0[src + c];
        }
    }
    for (int idx = gtid; idx < BB*NVV; idx += nthr) {
        int p = idx & (NVV-1), b = idx >> 13;
        int v = g_perm[p];
        int d = g_deg[v];
        for (int k = 0; k < d; k++) {
            int e = g_eid[k*NVV + v];
            g_rest[((size_t)b*ELLMAX + k)*NVV + p] = rest_len[e] * (1.f + act[(size_t)b*NEE + e]);
        }
    }
}

// ---------------- launch 3: persistent clustered solver ------------------------
__global__ void __launch_bounds__(TPB, 1) __cluster_dims__(NCTA, 1, 1)
k_main(float* __restrict__ out) {
    extern __shared__ float sm[];
    float2* s_pxy = (float2*)sm;          // NVP float2 (incl. sentinel)
    float*  s_pz  = sm + 2*NVP;           // NVP floats (incl. sentinel)
    __shared__ float s16[NW];
    __shared__ float s_ab[2];
    __shared__ float s_rs;
    __shared__ float s_mail[2];           // pAp partial mailbox, parity-buffered

    const int tid = threadIdx.x, cx = blockIdx.x, b = blockIdx.y;
    const int w = tid >> 5, l = tid & 31;
    const int base = b*NVV;

    // zero the sentinel slots (never rewritten: all updates touch [0,NVV))
    if (tid < NVP - NVV) {
        s_pxy[NVV + tid] = make_float2(0.f, 0.f);
        s_pz [NVV + tid] = 0.f;
    }

    // gather ownership: q = degree-quartile -> balanced warps & CTAs
    int pq[VPT], dq[VPT];
    float mmq[VPT];
    float PO[VPT][3], X[VPT][3];
    #pragma unroll
    for (int q = 0; q < VPT; q++) {
        int c = q*(NW*NCTA) + w*NCTA + cx;
        int p = c*32 + l;
        pq[q] = p;
        dq[q] = g_deg_p[p];
        mmq[q] = g_mass_p[p];
        int i = base + p;
        PO[q][0] = g_pos[i]; PO[q][1] = g_pos[CS+i]; PO[q][2] = g_pos[2*CS+i];
        X [q][0] = g_v0[i];  X [q][1] = g_v0[CS+i];  X [q][2] = g_v0[2*CS+i];
    }

    // register-resident residual: chunk j covers vertex j*TPB + tid
    float rX[NCH], rY[NCH], rZ[NCH];

    for (int s = 0; s < NSUB; s++) {
        // ---- stage pos into p region ----
        #pragma unroll
        for (int j = 0; j < NCH; j++) {
            int p = j*TPB + tid, i = base + p;
            s_pxy[p] = make_float2(__ldcg(&g_pos[i]), __ldcg(&g_pos[CS+i]));
            s_pz [p] = __ldcg(&g_pos[2*CS+i]);
        }
        __syncthreads();

        // ---- force, b = m v + dt f -> g_r slice (guarded tail) ----
        #pragma unroll
        for (int q = 0; q < VPT; q++) {
            int p = pq[q], i = base + p, d = dq[q];
            int np = (d + 1) >> 1;
            float fx = 0.f, fy = 0.f, fz = 0.f;
            const unsigned* nrow = &g_nbrp[p];
            unsigned cur = nrow[0];
            for (int kp = 0; kp < np; kp++) {
                unsigned nxt = (kp+1 < np) ? nrow[(kp+1)*NVV] : 0u;
                int u0 = cur & 0xffffu, u1 = cur >> 16;
                {
                    float2 t = s_pxy[u0];
                    float dx = PO[q][0] - t.x, dy = PO[q][1] - t.y, dz = PO[q][2] - s_pz[u0];
                    float len = sqrtf(dx*dx + dy*dy + dz*dz);
                    float rr = g_rest[((size_t)b*ELLMAX + 2*kp)*NVV + p];
                    float cc = -KSf * (len - rr) / fmaxf(len, 1e-6f);
                    fx += cc*dx; fy += cc*dy; fz += cc*dz;
                }
                if (2*kp + 1 < d) {
                    float2 t = s_pxy[u1];
                    float dx = PO[q][0] - t.x, dy = PO[q][1] - t.y, dz = PO[q][2] - s_pz[u1];
                    float len = sqrtf(dx*dx + dy*dy + dz*dz);
                    float rr = g_rest[((size_t)b*ELLMAX + 2*kp+1)*NVV + p];
                    float cc = -KSf * (len - rr) / fmaxf(len, 1e-6f);
                    fx += cc*dx; fy += cc*dy; fz += cc*dz;
                }
                cur = nxt;
            }
            float bx = mmq[q]*X[q][0] + DTf*fx;
            float by = mmq[q]*X[q][1] + DTf*(fy + mmq[q]*(-9.8f));
            float bz = mmq[q]*X[q][2] + DTf*fz;
            X[q][0] = 0.f; X[q][1] = 0.f; X[q][2] = 0.f;
            __stcg(&g_r[i], bx); __stcg(&g_r[CS+i], by); __stcg(&g_r[2*CS+i], bz);
        }
        CLUSTER_SYNC_();

        // ---- stage r -> registers, p -> smem; rs0 locally ----
        float rs_loc = 0.f;
        #pragma unroll
        for (int j = 0; j < NCH; j++) {
            int p = j*TPB + tid, i = base + p;
            float rx = __ldcg(&g_r[i]);
            float ry = __ldcg(&g_r[CS+i]);
            float rz = __ldcg(&g_r[2*CS+i]);
            rX[j] = rx; rY[j] = ry; rZ[j] = rz;
            s_pxy[p] = make_float2(rx, ry); s_pz[p] = rz;
            rs_loc += rx*rx + ry*ry + rz*rz;
        }
        __syncthreads();
        {
            float t = bredt(rs_loc, s16);
            if (tid == 0) s_rs = t;
        }
        __syncthreads();

        // ---- CG iterations ----
        for (int it = 0; it < CG_ITERS; it++) {
            const int par = it & 1;
            float4* Ap = g_Ap4[par];

            // matvec: sentinel-padded; cache pv in regs for the x-update
            float pvx[VPT], pvy[VPT], pvz[VPT];
            float pap = 0.f;
            #pragma unroll
            for (int q = 0; q < VPT; q++) {
                int p = pq[q], i = base + p, d = dq[q];
                int np = (d + 1) >> 1;
                float sx = 0.f, sy = 0.f, sz = 0.f;
                const unsigned* nrow = &g_nbrp[p];
                unsigned cur = nrow[0];
                for (int kp = 0; kp < np; kp++) {
                    unsigned nxt = (kp+1 < np) ? nrow[(kp+1)*NVV] : 0u;
                    int u0 = cur & 0xffffu, u1 = cur >> 16;
                    float2 t0 = s_pxy[u0];
                    sx += t0.x; sy += t0.y; sz += s_pz[u0];
                    float2 t1 = s_pxy[u1];          // sentinel -> (+0,+0,+0), exact
                    sx += t1.x; sy += t1.y; sz += s_pz[u1];
                    cur = nxt;
                }
                float2 pv = s_pxy[p]; float pz = s_pz[p];
                pvx[q] = pv.x; pvy[q] = pv.y; pvz[q] = pz;
                float md = mmq[q] + (float)d;
                float ax = md*pv.x - sx;
                float ay = md*pv.y - sy;
                float az = md*pz   - sz;
                __stcg(&Ap[i], make_float4(ax, ay, az, 0.f));
                pap += pv.x*ax + pv.y*ay + pz*az;
            }
            {
                float t = bredt(pap, s16);
                if (tid == 0) s_mail[par] = t;
            }
            CLUSTER_SYNC_();                     // publishes s_mail + Ap slices

            // alpha: lanes 0..3 of warp 0 read the 4 rank mailboxes in parallel
            if (w == 0) {
                float v = 0.f;
                if (l < NCTA) {
                    uint32_t ma = (uint32_t)__cvta_generic_to_shared(&s_mail[par]);
                    v = dsmem_read_f32(ma, (uint32_t)l);
                }
                #pragma unroll
                for (int o = 2; o; o >>= 1) v += __shfl_down_sync(0xffffffffu, v, o);
                if (l == 0) s_ab[0] = s_rs / (v + 1e-12f);
            }
            __syncthreads();
            float alpha = s_ab[0];

            // x += alpha p (pv cached in registers; no smem reads)
            #pragma unroll
            for (int q = 0; q < VPT; q++) {
                X[q][0] += alpha*pvx[q]; X[q][1] += alpha*pvy[q]; X[q][2] += alpha*pvz[q];
            }

            if (it < CG_ITERS - 1) {
                // sweep1 (registers only): r -= alpha Ap; rs_new from stored r
                float rsn_loc = 0.f;
                #pragma unroll
                for (int j = 0; j < NCH; j++) {
                    int i = base + j*TPB + tid;
                    float4 a4 = __ldcg(&Ap[i]);
                    float rx = rX[j] - alpha*a4.x;
                    float ry = rY[j] - alpha*a4.y;
                    float rz = rZ[j] - alpha*a4.z;
                    rX[j] = rx; rY[j] = ry; rZ[j] = rz;
                    rsn_loc += rx*rx + ry*ry + rz*rz;
                }
                __syncthreads();
                {
                    float t = bredt(rsn_loc, s16);
                    if (tid == 0) { s_ab[1] = t / (s_rs + 1e-12f); s_rs = t; }
                }
                __syncthreads();
                float beta = s_ab[1];
                // sweep2: p = r + beta p (r from regs; p in smem)
                #pragma unroll
                for (int j = 0; j < NCH; j++) {
                    int p = j*TPB + tid;
                    float2 po = s_pxy[p]; float poz = s_pz[p];
                    s_pxy[p] = make_float2(fmaf(beta, po.x, rX[j]),
                                           fmaf(beta, po.y, rY[j]));
                    s_pz [p] = fmaf(beta, poz, rZ[j]);
                }
                __syncthreads();
            }
        }

        // ---- pos += dt x ; emit trajectory ----
        #pragma unroll
        for (int q = 0; q < VPT; q++) {
            int p = pq[q], i = base + p;
            PO[q][0] += DTf*X[q][0];
            PO[q][1] += DTf*X[q][1];
            PO[q][2] += DTf*X[q][2];
            __stcg(&g_pos[i],      PO[q][0]);
            __stcg(&g_pos[CS+i],   PO[q][1]);
            __stcg(&g_pos[2*CS+i], PO[q][2]);
            int vorig = g_perm[p];
            size_t o = (((size_t)b*NSUB + s)*NVV + vorig)*3;
            out[o+0] = PO[q][0]; out[o+1] = PO[q][1]; out[o+2] = PO[q][2];
        }
        CLUSTER_SYNC_();
    }
}

// ---------------- launch -------------------------------------------------------
extern "C" void kernel_launch(void* const* d_in, const int* in_sizes, int n_in,
                              void* d_out, int out_size) {
    const float* act   = (const float*)d_in[0];
    const float* pos0  = (const float*)d_in[1];
    const float* vel0  = (const float*)d_in[2];
    const float* rlen  = (const float*)d_in[3];
    const float* mass  = (const float*)d_in[4];
    const int*   ei    = (const int*)d_in[5];
    const int*   ej    = (const int*)d_in[6];
    float*       out   = (float*)d_out;

    const int smbytes = 3*NVP*sizeof(float);   // ~96.2 KB (p only; r in regs)
    static int attr_done = 0;
    if (!attr_done) {
        cudaFuncSetAttribute(k_main, cudaFuncAttributeMaxDynamicSharedMemorySize, smbytes);
        attr_done = 1;
    }

    k_pre  <<<(NVV+255)/256, 256>>>();
    k_fill <<<(NEE+255)/256, 256>>>(ei, ej);
    k_setup<<<32, 1024>>>(mass, pos0, vel0, rlen, act);
    k_main <<<dim3(NCTA, BB), TPB, smbytes>>>(out);
}

// round 17
// speedup vs baseline: 1.1279x; 1.0004x over previous
#include <cuda_runtime.h>
#include <cstdint>

#define BB 32
#define NVV 8192
#define NEE 65536
#define ELLMAX 48
#define KPAIR 24        // ELLMAX/2 index pairs
#define NSUB 8
#define NCTA 4          // CTAs per batch = one cluster
#define TPB 512
#define VPT 4           // gather vertices per thread
#define NCH 16          // full-vector chunks per thread (NVV/TPB)
#define NW 16           // warps per CTA
#define CG_ITERS 20
#define DTf 0.01f
#define KSf 10000.0f
#define CS (BB*NVV)
#define NVP 8208        // NVV + 16 sentinel slots for smem p arrays

// ---------------- scratch ----------------------------------------------------
__device__ float    g_pos[3*CS];       // sorted space, planar
__device__ float    g_v0 [3*CS];
__device__ float    g_r  [3*CS];
__device__ float4   g_Ap4[2][CS];      // vectorized Ap, double-buffered
__device__ int      g_cnt[NVV];
__device__ int      g_deg[NVV];
__device__ int      g_nbr[ELLMAX*NVV];
__device__ int      g_eid[ELLMAX*NVV];
__device__ int      g_perm[NVV];
__device__ int      g_ipos[NVV];
__device__ unsigned g_nbrp[KPAIR*NVV]; // packed sorted-position pairs (sentinel-padded)
__device__ float    g_mass_p[NVV];
__device__ int      g_deg_p[NVV];
__device__ float    g_rest[(size_t)BB*ELLMAX*NVV];
__device__ unsigned g_gbar;

// ---------------- helpers ----------------------------------------------------
__device__ __forceinline__ void gpu_spin_barrier(unsigned* bar, unsigned target) {
    __syncthreads();
    if (threadIdx.x == 0) {
        asm volatile("red.release.gpu.add.u32 [%0], 1;" :: "l"(bar) : "memory");
        unsigned v;
        do {
            asm volatile("ld.acquire.gpu.u32 %0, [%1];" : "=r"(v) : "l"(bar) : "memory");
        } while (v < target);
    }
    __syncthreads();
}

#define CLUSTER_SYNC_() do { \
    asm volatile("barrier.cluster.arrive.aligned;" ::: "memory"); \
    asm volatile("barrier.cluster.wait.aligned;"   ::: "memory"); \
} while (0)

__device__ __forceinline__ void dsmem_write_f32(uint32_t saddr, uint32_t rank, float v) {
    uint32_t ra;
    asm volatile("mapa.shared::cluster.u32 %0, %1, %2;" : "=r"(ra) : "r"(saddr), "r"(rank));
    asm volatile("st.shared::cluster.f32 [%0], %1;" :: "r"(ra), "f"(v) : "memory");
}

// symmetric block all-reduce over 512 threads: every thread gets the same total
// (warp shuffle -> s16[w] -> one sync -> fixed-order serial sum of 16 slots)
__device__ __forceinline__ float allred(float a, float* s16) {
    int lane = threadIdx.x & 31, w = threadIdx.x >> 5;
    #pragma unroll
    for (int o = 16; o; o >>= 1) a += __shfl_down_sync(0xffffffffu, a, o);
    if (lane == 0) s16[w] = a;
    __syncthreads();
    float t = 0.f;
    #pragma unroll
    for (int k = 0; k < NW; k++) t += s16[k];
    return t;
}

// ---------------- launch 0: zero ---------------------------------------------
__global__ void k_pre() {
    int v = blockIdx.x * blockDim.x + threadIdx.x;
    if (v < NVV) g_cnt[v] = 0;
    if (v == 0)  g_gbar = 0u;
}

// ---------------- launch 1: adjacency fill -----------------------------------
__global__ void k_fill(const int* __restrict__ ei, const int* __restrict__ ej) {
    int e = blockIdx.x * blockDim.x + threadIdx.x;
    if (e >= NEE) return;
    int i = ei[e], j = ej[e];
    int si = atomicAdd(&g_cnt[i], 1);
    if (si < ELLMAX) { g_nbr[si*NVV + i] = j; g_eid[si*NVV + i] = e; }
    int sj = atomicAdd(&g_cnt[j], 1);
    if (sj < ELLMAX) { g_nbr[sj*NVV + j] = i; g_eid[sj*NVV + j] = e; }
}

// ---------------- launch 2: fused setup ---------------------------------------
__global__ void k_setup(const float* __restrict__ mass,
                        const float* __restrict__ pos0, const float* __restrict__ vel0,
                        const float* __restrict__ rest_len, const float* __restrict__ act) {
    const int gtid = blockIdx.x * blockDim.x + threadIdx.x;
    const int nthr = gridDim.x * blockDim.x;

    // phase 1: deterministic per-vertex adjacency sort
    for (int v = gtid; v < NVV; v += nthr) {
        int d = min(g_cnt[v], ELLMAX);
        g_deg[v] = d;
        long long key[ELLMAX];
        for (int k = 0; k < d; k++)
            key[k] = ((long long)g_nbr[k*NVV + v] << 32) | (unsigned)g_eid[k*NVV + v];
        for (int a = 1; a < d; a++) {
            long long t = key[a]; int c = a - 1;
            while (c >= 0 && key[c] > t) { key[c+1] = key[c]; c--; }
            key[c+1] = t;
        }
        for (int k = 0; k < d; k++) {
            g_nbr[k*NVV + v] = (int)(key[k] >> 32);
            g_eid[k*NVV + v] = (int)(key[k] & 0xffffffffLL);
        }
    }
    gpu_spin_barrier(&g_gbar, gridDim.x * 1u);

    // phase 2: stable counting sort by degree (CTA 0)
    if (blockIdx.x == 0) {
        __shared__ int s_cnt[64], s_off[64];
        int w = threadIdx.x >> 5, l = threadIdx.x & 31;
        #pragma unroll
        for (int pass = 0; pass < 2; pass++) {
            int d = w + pass*32;
            int cnt = 0;
            for (int b0 = 0; b0 < NVV; b0 += 32) {
                int dg = g_deg[b0 + l];
                unsigned m = __ballot_sync(0xffffffffu, dg == d);
                cnt += __popc(m);
            }
            if (l == 0) s_cnt[d] = cnt;
        }
        __syncthreads();
        if (threadIdx.x == 0) {
            int o = 0;
            for (int d = 0; d < 64; d++) { s_off[d] = o; o += s_cnt[d]; }
        }
        __syncthreads();
        #pragma unroll
        for (int pass = 0; pass < 2; pass++) {
            int d = w + pass*32;
            int off = s_off[d];
            for (int b0 = 0; b0 < NVV; b0 += 32) {
                int v = b0 + l;
                int dg = g_deg[v];
                unsigned m = __ballot_sync(0xffffffffu, dg == d);
                if (dg == d) {
                    int rank = __popc(m & ((1u << l) - 1u));
                    g_perm[off + rank] = v;
                    g_ipos[v] = off + rank;
                }
                off += __popc(m);
            }
        }
    }
    gpu_spin_barrier(&g_gbar, gridDim.x * 2u);

    // phase 3: sorted-space tables; odd tails padded with sentinel index NVV
    for (int p = gtid; p < NVV; p += nthr) {
        int v = g_perm[p];
        g_mass_p[p] = mass[v];
        int d = g_deg[v];
        g_deg_p[p] = d;
        for (int kp = 0; kp < KPAIR; kp++) {
            unsigned lo = (2*kp   < d) ? (unsigned)g_ipos[g_nbr[(2*kp  )*NVV + v]] : (unsigned)NVV;
            unsigned hi = (2*kp+1 < d) ? (unsigned)g_ipos[g_nbr[(2*kp+1)*NVV + v]] : (unsigned)NVV;
            g_nbrp[kp*NVV + p] = lo | (hi << 16);
        }
    }
    for (int idx = gtid; idx < CS; idx += nthr) {
        int p = idx & (NVV-1), b = idx >> 13;
        int v = g_perm[p];
        size_t src = ((size_t)b*NVV + v)*3;
        #pragma unroll
        for (int c = 0; c < 3; c++) {
            g_pos[c*CS + idx] = pos0[src + c];
            g_v0 [c*CS + idx] = vel0[src + c];
        }
    }
    for (int idx = gtid; idx < BB*NVV; idx += nthr) {
        int p = idx & (NVV-1), b = idx >> 13;
        int v = g_perm[p];
        int d = g_deg[v];
        for (int k = 0; k < d; k++) {
            int e = g_eid[k*NVV + v];
            g_rest[((size_t)b*ELLMAX + k)*NVV + p] = rest_len[e] * (1.f + act[(size_t)b*NEE + e]);
        }
    }
}

// ---------------- launch 3: persistent clustered solver ------------------------
__global__ void __launch_bounds__(TPB, 1) __cluster_dims__(NCTA, 1, 1)
k_main(float* __restrict__ out) {
    extern __shared__ float sm[];
    float2* s_pxy = (float2*)sm;          // NVP float2 (incl. sentinel)
    float*  s_pz  = sm + 2*NVP;           // NVP floats (incl. sentinel)
    __shared__ float s16a[NW];            // rs0 / rsn all-reduce buffer
    __shared__ float s16b[NW];            // pAp all-reduce buffer
    __shared__ float s_mail4[2][NCTA];    // pushed pAp totals, parity-buffered

    const int tid = threadIdx.x, cx = blockIdx.x, b = blockIdx.y;
    const int w = tid >> 5, l = tid & 31;
    const int base = b*NVV;

    // zero the sentinel slots (never rewritten: all updates touch [0,NVV))
    if (tid < NVP - NVV) {
        s_pxy[NVV + tid] = make_float2(0.f, 0.f);
        s_pz [NVV + tid] = 0.f;
    }

    // gather ownership: q = degree-quartile -> balanced warps & CTAs
    int pq[VPT], dq[VPT];
    float mmq[VPT];
    float PO[VPT][3], X[VPT][3];
    #pragma unroll
    for (int q = 0; q < VPT; q++) {
        int c = q*(NW*NCTA) + w*NCTA + cx;
        int p = c*32 + l;
        pq[q] = p;
        dq[q] = g_deg_p[p];
        mmq[q] = g_mass_p[p];
        int i = base + p;
        PO[q][0] = g_pos[i]; PO[q][1] = g_pos[CS+i]; PO[q][2] = g_pos[2*CS+i];
        X [q][0] = g_v0[i];  X [q][1] = g_v0[CS+i];  X [q][2] = g_v0[2*CS+i];
    }

    // register-resident residual: chunk j covers vertex j*TPB + tid
    float rX[NCH], rY[NCH], rZ[NCH];

    for (int s = 0; s < NSUB; s++) {
        // ---- stage pos into p region ----
        #pragma unroll
        for (int j = 0; j < NCH; j++) {
            int p = j*TPB + tid, i = base + p;
            s_pxy[p] = make_float2(__ldcg(&g_pos[i]), __ldcg(&g_pos[CS+i]));
            s_pz [p] = __ldcg(&g_pos[2*CS+i]);
        }
        __syncthreads();

        // ---- force, b = m v + dt f -> g_r slice (guarded tail) ----
        #pragma unroll
        for (int q = 0; q < VPT; q++) {
            int p = pq[q], i = base + p, d = dq[q];
            int np = (d + 1) >> 1;
            float fx = 0.f, fy = 0.f, fz = 0.f;
            const unsigned* nrow = &g_nbrp[p];
            unsigned cur = nrow[0];
            for (int kp = 0; kp < np; kp++) {
                unsigned nxt = (kp+1 < np) ? nrow[(kp+1)*NVV] : 0u;
                int u0 = cur & 0xffffu, u1 = cur >> 16;
                {
                    float2 t = s_pxy[u0];
                    float dx = PO[q][0] - t.x, dy = PO[q][1] - t.y, dz = PO[q][2] - s_pz[u0];
                    float len = sqrtf(dx*dx + dy*dy + dz*dz);
                    float rr = g_rest[((size_t)b*ELLMAX + 2*kp)*NVV + p];
                    float cc = -KSf * (len - rr) / fmaxf(len, 1e-6f);
                    fx += cc*dx; fy += cc*dy; fz += cc*dz;
                }
                if (2*kp + 1 < d) {
                    float2 t = s_pxy[u1];
                    float dx = PO[q][0] - t.x, dy = PO[q][1] - t.y, dz = PO[q][2] - s_pz[u1];
                    float len = sqrtf(dx*dx + dy*dy + dz*dz);
                    float rr = g_rest[((size_t)b*ELLMAX + 2*kp+1)*NVV + p];
                    float cc = -KSf * (len - rr) / fmaxf(len, 1e-6f);
                    fx += cc*dx; fy += cc*dy; fz += cc*dz;
                }
                cur = nxt;
            }
            float bx = mmq[q]*X[q][0] + DTf*fx;
            float by = mmq[q]*X[q][1] + DTf*(fy + mmq[q]*(-9.8f));
            float bz = mmq[q]*X[q][2] + DTf*fz;
            X[q][0] = 0.f; X[q][1] = 0.f; X[q][2] = 0.f;
            __stcg(&g_r[i], bx); __stcg(&g_r[CS+i], by); __stcg(&g_r[2*CS+i], bz);
        }
        CLUSTER_SYNC_();

        // ---- stage r -> registers, p -> smem; rs0 via symmetric all-reduce ----
        float rs_loc = 0.f;
        #pragma unroll
        for (int j = 0; j < NCH; j++) {
            int p = j*TPB + tid, i = base + p;
            float rx = __ldcg(&g_r[i]);
            float ry = __ldcg(&g_r[CS+i]);
            float rz = __ldcg(&g_r[2*CS+i]);
            rX[j] = rx; rY[j] = ry; rZ[j] = rz;
            s_pxy[p] = make_float2(rx, ry); s_pz[p] = rz;
            rs_loc += rx*rx + ry*ry + rz*rz;
        }
        float rs = allred(rs_loc, s16a);   // sync inside also covers s_p staging

        // ---- CG iterations ----
        for (int it = 0; it < CG_ITERS; it++) {
            const int par = it & 1;
            float4* Ap = g_Ap4[par];

            // matvec: sentinel-padded; cache pv in regs for the x-update
            float pvx[VPT], pvy[VPT], pvz[VPT];
            float pap = 0.f;
            #pragma unroll
            for (int q = 0; q < VPT; q++) {
                int p = pq[q], i = base + p, d = dq[q];
                int np = (d + 1) >> 1;
                float sx = 0.f, sy = 0.f, sz = 0.f;
                const unsigned* nrow = &g_nbrp[p];
                unsigned cur = nrow[0];
                for (int kp = 0; kp < np; kp++) {
                    unsigned nxt = (kp+1 < np) ? nrow[(kp+1)*NVV] : 0u;
                    int u0 = cur & 0xffffu, u1 = cur >> 16;
                    float2 t0 = s_pxy[u0];
                    sx += t0.x; sy += t0.y; sz += s_pz[u0];
                    float2 t1 = s_pxy[u1];          // sentinel -> (+0,+0,+0), exact
                    sx += t1.x; sy += t1.y; sz += s_pz[u1];
                    cur = nxt;
                }
                float2 pv = s_pxy[p]; float pz = s_pz[p];
                pvx[q] = pv.x; pvy[q] = pv.y; pvz[q] = pz;
                float md = mmq[q] + (float)d;
                float ax = md*pv.x - sx;
                float ay = md*pv.y - sy;
                float az = md*pz   - sz;
                __stcg(&Ap[i], make_float4(ax, ay, az, 0.f));
                pap += pv.x*ax + pv.y*ay + pz*az;
            }
            float pap_tot = allred(pap, s16b);
            // push own total to all 4 ranks' mailboxes (visible after cluster barrier)
            if (tid < NCTA) {
                uint32_t ma = (uint32_t)__cvta_generic_to_shared(&s_mail4[par][cx]);
                dsmem_write_f32(ma, (uint32_t)tid, pap_tot);
            }
            CLUSTER_SYNC_();                     // publishes mailboxes + Ap slices

            // alpha locally on every thread (4 broadcast LDS reads, fixed order)
            float sp = s_mail4[par][0] + s_mail4[par][1]
                     + s_mail4[par][2] + s_mail4[par][3];
            float alpha = rs / (sp + 1e-12f);

            // x += alpha p (pv cached in registers; no smem reads)
            #pragma unroll
            for (int q = 0; q < VPT; q++) {
                X[q][0] += alpha*pvx[q]; X[q][1] += alpha*pvy[q]; X[q][2] += alpha*pvz[q];
            }

            if (it < CG_ITERS - 1) {
                // sweep1 (registers only): r -= alpha Ap; rs_new from stored r
                float rsn_loc = 0.f;
                #pragma unroll
                for (int j = 0; j < NCH; j++) {
                    int i = base + j*TPB + tid;
                    float4 a4 = __ldcg(&Ap[i]);
                    float rx = rX[j] - alpha*a4.x;
                    float ry = rY[j] - alpha*a4.y;
                    float rz = rZ[j] - alpha*a4.z;
                    rX[j] = rx; rY[j] = ry; rZ[j] = rz;
                    rsn_loc += rx*rx + ry*ry + rz*rz;
                }
                float rsn = allred(rsn_loc, s16a);
                float beta = rsn / (rs + 1e-12f);
                rs = rsn;
                // sweep2: p = r + beta p (r from regs; p in smem)
                #pragma unroll
                for (int j = 0; j < NCH; j++) {
                    int p = j*TPB + tid;
                    float2 po = s_pxy[p]; float poz = s_pz[p];
                    s_pxy[p] = make_float2(fmaf(beta, po.x, rX[j]),
                                           fmaf(beta, po.y, rY[j]));
                    s_pz [p] = fmaf(beta, poz, rZ[j]);
                }
                __syncthreads();
            }
        }

        // ---- pos += dt x ; emit trajectory ----
        #pragma unroll
        for (int q = 0; q < VPT; q++) {
            int p = pq[q], i = base + p;
            PO[q][0] += DTf*X[q][0];
            PO[q][1] += DTf*X[q][1];
            PO[q][2] += DTf*X[q][2];
            __stcg(&g_pos[i],      PO[q][0]);
            __stcg(&g_pos[CS+i],   PO[q][1]);
            __stcg(&g_pos[2*CS+i], PO[q][2]);
            int vorig = g_perm[p];
            size_t o = (((size_t)b*NSUB + s)*NVV + vorig)*3;
            out[o+0] = PO[q][0]; out[o+1] = PO[q][1]; out[o+2] = PO[q][2];
        }
        CLUSTER_SYNC_();
    }
}

// ---------------- launch -------------------------------------------------------
extern "C" void kernel_launch(void* const* d_in, const int* in_sizes, int n_in,
                              void* d_out, int out_size) {
    const float* act   = (const float*)d_in[0];
    const float* pos0  = (const float*)d_in[1];
    const float* vel0  = (const float*)d_in[2];
    const float* rlen  = (const float*)d_in[3];
    const float* mass  = (const float*)d_in[4];
    const int*   ei    = (const int*)d_in[5];
    const int*   ej    = (const int*)d_in[6];
    float*       out   = (float*)d_out;

    const int smbytes = 3*NVP*sizeof(float);   // ~96.2 KB (p only; r in regs)
    static int attr_done = 0;
    if (!attr_done) {
        cudaFuncSetAttribute(k_main, cudaFuncAttributeMaxDynamicSharedMemorySize, smbytes);
        attr_done = 1;
    }

    k_pre  <<<(NVV+255)/256, 256>>>();
    k_fill <<<(NEE+255)/256, 256>>>(ei, ej);
    k_setup<<<32, 1024>>>(mass, pos0, vel0, rlen, act);
    k_main <<<dim3(NCTA, BB), TPB, smbytes>>>(out);
}